// round 7
// baseline (speedup 1.0000x reference)
#include <cuda_runtime.h>

// LengthRegulator v3: register-resident cumsum + direct scatter into shared tile.
//
//   cs = inclusive cumsum(dur[b]);  out[b,p] = (p < cs[N-1]) ? token(p)+1 : 0
//
// v2.1 (10.3us) still published the full cumsum to shared with 16-way bank
// conflicts (s_cs[tid*16+i], 64B thread stride) and searched/scattered through
// it (L1=34.6%). v3 removes s_cs entirely: each thread keeps its 16 tokens'
// cumsum in registers and clips its own runs against the CTA's output window,
// writing directly into the zeroed s_out tile. No publish, no binary search,
// 8KB smem instead of 25KB.

#define N_TOK       4096
#define THREADS     256
#define PER_THREAD  (N_TOK / THREADS)      // 16 tokens per thread
#define OUT_PER_CTA 2048

__global__ __launch_bounds__(THREADS)
void lr_regscatter_kernel(const int* __restrict__ dur,
                          float* __restrict__ out,
                          int T, int nblk) {
    const int b     = blockIdx.x / nblk;
    const int chunk = blockIdx.x % nblk;
    const int tid   = threadIdx.x;
    const int lane  = tid & 31;
    const int wid   = tid >> 5;

    __shared__ float s_out[OUT_PER_CTA];
    __shared__ int   s_wsum[THREADS / 32];
    __shared__ int   s_woff[THREADS / 32 + 1];   // [8] = block total

    // ---- 1) load 16 contiguous durations per thread, local inclusive scan ----
    int v[PER_THREAD];
    {
        const int4* d4 = (const int4*)(dur + b * N_TOK) + tid * 4;
        int4 a = d4[0], c = d4[1], e = d4[2], f = d4[3];
        v[0]  = a.x; v[1]  = a.y; v[2]  = a.z; v[3]  = a.w;
        v[4]  = c.x; v[5]  = c.y; v[6]  = c.z; v[7]  = c.w;
        v[8]  = e.x; v[9]  = e.y; v[10] = e.z; v[11] = e.w;
        v[12] = f.x; v[13] = f.y; v[14] = f.z; v[15] = f.w;
    }
    #pragma unroll
    for (int i = 1; i < PER_THREAD; i++) v[i] += v[i - 1];
    const int my_total = v[PER_THREAD - 1];

    // ---- 2) warp inclusive scan of per-thread totals ----
    int s = my_total;
    #pragma unroll
    for (int o = 1; o < 32; o <<= 1) {
        int u = __shfl_up_sync(0xffffffffu, s, o);
        if (lane >= o) s += u;
    }
    if (lane == 31) s_wsum[wid] = s;

    // zero the output tile while the scan settles (8 floats / thread)
    #pragma unroll
    for (int k = 0; k < OUT_PER_CTA / THREADS; k++)
        s_out[k * THREADS + tid] = 0.0f;
    __syncthreads();

    // ---- 3) serial scan of the 8 warp totals ----
    if (tid == 0) {
        int acc = 0;
        #pragma unroll
        for (int w = 0; w < THREADS / 32; w++) { s_woff[w] = acc; acc += s_wsum[w]; }
        s_woff[THREADS / 32] = acc;              // row total
    }
    __syncthreads();

    const int base  = s_woff[wid] + (s - my_total);   // exclusive prefix for this thread
    const int total = s_woff[THREADS / 32];

    // ---- 4) scatter: clip this thread's 16 runs against the CTA window ----
    const int p0 = chunk * OUT_PER_CTA;
    int p1 = p0 + OUT_PER_CTA;
    if (p1 > T)     p1 = T;
    if (p1 > total) p1 = total;

    // thread's tokens span [base, base + my_total) — skip if disjoint from window
    if (base < p1 && base + my_total > p0) {
        const int tok0 = tid * PER_THREAD;
        int prev = 0;
        #pragma unroll
        for (int i = 0; i < PER_THREAD; i++) {
            int st = base + prev;       // exclusive start of token i's run
            int en = base + v[i];       // exclusive end
            prev = v[i];
            if (st < p0) st = p0;
            if (en > p1) en = p1;
            const float val = (float)(tok0 + i + 1);
            for (int p = st; p < en; p++)
                s_out[p - p0] = val;
        }
    }
    __syncthreads();

    // ---- 5) stream the tile to global, scalar coalesced (alignment-proof) ----
    float* orow = out + b * T;
    #pragma unroll
    for (int k = 0; k < OUT_PER_CTA / THREADS; k++) {
        const int idx = k * THREADS + tid;
        const int p   = p0 + idx;
        if (p < T) orow[p] = s_out[idx];
    }
}

extern "C" void kernel_launch(void* const* d_in, const int* in_sizes, int n_in,
                              void* d_out, int out_size) {
    const int* dur = (const int*)d_in[0];
    float*     out = (float*)d_out;
    const int  B    = 32;
    const int  T    = out_size / B;
    const int  nblk = (T + OUT_PER_CTA - 1) / OUT_PER_CTA;

    lr_regscatter_kernel<<<B * nblk, THREADS>>>(dur, out, T, nblk);
}

// round 9
// speedup vs baseline: 1.0717x; 1.0717x over previous
#include <cuda_runtime.h>

// LengthRegulator v4 (R9 = infra retry of R8, kernel unchanged):
// conflict-free padded cumsum publish + parallel token scatter DIRECTLY to
// global (no shared staging tile).
//
// Cost model from R6/R7: the per-SM smem crossbar was the bottleneck —
// v2's publish was 16-way bank conflicted (~2048 slots/CTA), v3's scatter was
// single-lane serialized (~2048 slots/CTA). v4 pads the publish to stride 17
// (conflict-free, 128 slots) and scatters runs straight to gmem (no crossbar).
//
//   cs = inclusive cumsum(dur[b]);  token t owns out[b, cs[t-1] .. cs[t])
//   out[b,p] = t+1 there, 0 for p >= cs[N-1].

#define N_TOK       4096
#define THREADS     256
#define PER_THREAD  (N_TOK / THREADS)          // 16 tokens per thread
#define OUT_PER_CTA 2048
#define PAD(t)      ((((t) >> 4) * 17) + ((t) & 15))   // padded cumsum index

__global__ __launch_bounds__(THREADS)
void lr_v4_kernel(const int* __restrict__ dur,
                  float* __restrict__ out,
                  int T, int nblk) {
    const int b     = blockIdx.x / nblk;
    const int chunk = blockIdx.x % nblk;
    const int tid   = threadIdx.x;
    const int lane  = tid & 31;
    const int wid   = tid >> 5;

    __shared__ int s_cs[THREADS * 17];          // padded: thread t -> [t*17 .. t*17+15]
    __shared__ int s_wsum[THREADS / 32];
    __shared__ int s_woff[THREADS / 32 + 1];    // [8] = row total

    // ---- 1) load 16 contiguous durations per thread, local inclusive scan ----
    int v[PER_THREAD];
    {
        const int4* d4 = (const int4*)(dur + b * N_TOK) + tid * 4;
        int4 a = d4[0], c = d4[1], e = d4[2], f = d4[3];
        v[0]  = a.x; v[1]  = a.y; v[2]  = a.z; v[3]  = a.w;
        v[4]  = c.x; v[5]  = c.y; v[6]  = c.z; v[7]  = c.w;
        v[8]  = e.x; v[9]  = e.y; v[10] = e.z; v[11] = e.w;
        v[12] = f.x; v[13] = f.y; v[14] = f.z; v[15] = f.w;
    }
    #pragma unroll
    for (int i = 1; i < PER_THREAD; i++) v[i] += v[i - 1];
    const int my_total = v[PER_THREAD - 1];

    // ---- 2) warp inclusive scan of per-thread totals ----
    int s = my_total;
    #pragma unroll
    for (int o = 1; o < 32; o <<= 1) {
        int u = __shfl_up_sync(0xffffffffu, s, o);
        if (lane >= o) s += u;
    }
    if (lane == 31) s_wsum[wid] = s;
    __syncthreads();

    // ---- 3) serial scan of the 8 warp totals ----
    if (tid == 0) {
        int acc = 0;
        #pragma unroll
        for (int w = 0; w < THREADS / 32; w++) { s_woff[w] = acc; acc += s_wsum[w]; }
        s_woff[THREADS / 32] = acc;
    }
    __syncthreads();

    const int base  = s_woff[wid] + (s - my_total);   // exclusive prefix for this thread
    const int total = s_woff[THREADS / 32];

    // ---- 4) publish inclusive cumsum, padded stride 17 (conflict-free) ----
    #pragma unroll
    for (int i = 0; i < PER_THREAD; i++)
        s_cs[tid * 17 + i] = base + v[i];
    __syncthreads();

    // ---- 5) window bounds ----
    const int p0    = chunk * OUT_PER_CTA;
    const int p_end = (p0 + OUT_PER_CTA < T) ? p0 + OUT_PER_CTA : T;   // window end
    int p1 = p_end;
    if (p1 > total) p1 = total;                                        // last valued pos

    // ---- 6) parallel scatter: tokens strided across threads, runs -> gmem ----
    float* orow = out + b * T;
    if (p0 < p1) {
        // first token with cs[t] > p0 — same path for all threads (broadcast LDS)
        int lo = 0, hi = N_TOK;
        #pragma unroll
        for (int it = 0; it < 12; it++) {
            const int mid = (lo + hi) >> 1;
            if (s_cs[PAD(mid)] > p0) hi = mid; else lo = mid + 1;
        }
        for (int t = lo + tid; t < N_TOK; t += THREADS) {
            const int st = (t == 0) ? 0 : s_cs[PAD(t - 1)];
            if (st >= p1) break;                      // monotone cs: safe per-thread
            int en = s_cs[PAD(t)];
            if (en > p1) en = p1;
            const float val = (float)(t + 1);
            for (int p = (st > p0 ? st : p0); p < en; p++)
                orow[p] = val;
        }
    }

    // ---- 7) zero-fill tail of this window: [max(p0,total), p_end) ----
    const int z0 = (p0 > total) ? p0 : total;
    for (int p = z0 + tid; p < p_end; p += THREADS)
        orow[p] = 0.0f;
}

extern "C" void kernel_launch(void* const* d_in, const int* in_sizes, int n_in,
                              void* d_out, int out_size) {
    const int* dur = (const int*)d_in[0];
    float*     out = (float*)d_out;
    const int  B    = 32;
    const int  T    = out_size / B;
    const int  nblk = (T + OUT_PER_CTA - 1) / OUT_PER_CTA;

    lr_v4_kernel<<<B * nblk, THREADS>>>(dur, out, T, nblk);
}